// round 14
// baseline (speedup 1.0000x reference)
#include <cuda_runtime.h>
#include <cuda_bf16.h>

// ShiftImgPreprocessor: out[b,t,c,i,j] = img[b,t,c, clamp(i+sy-PAD,0,H-1),
//                                              clamp(j+sx-PAD,0,W-1)] / 255 - 0.5
// img (256,4,3,96,96) fp32, shift (256,2) int32 (sx=shift[b][0], sy=shift[b][1]).
//
// R13: combine R5's deep MLP (8 rows/warp -> 24 front-batched independent
// loads per lane) with R4-class occupancy by using 128-thread blocks
// (4 warps, 32 rows/block). R5's 256-thread/64-row blocks dropped occ to 59%
// and capped in-flight bytes; smaller CTAs pack better per SM. Plain loads
// and aligned warp-contiguous STG.32 stores (L2 policy hints proven dead in
// R7-R9).

#define PAD 4
#define N_IMG 256
#define T_IMG 4
#define C_IMG 3
#define H_IMG 96
#define W_IMG 96
#define TC (T_IMG * C_IMG)                    // 12 planes per batch
#define N_PLANES (N_IMG * TC)                 // 3072
#define ROWS_PER_WARP 8
#define WARPS_PER_BLOCK 4
#define THREADS (WARPS_PER_BLOCK * 32)        // 128
#define ROWS_PER_BLOCK (WARPS_PER_BLOCK * ROWS_PER_WARP)   // 32
#define TOTAL_ROWS (N_PLANES * H_IMG)         // 294912
#define NBLOCKS (TOTAL_ROWS / ROWS_PER_BLOCK) // 9216

__global__ __launch_bounds__(THREADS) void shift_img_kernel(
    const float* __restrict__ img,
    const int*   __restrict__ shift,
    float*       __restrict__ out)
{
    const int warp = threadIdx.x >> 5;
    const int lane = threadIdx.x & 31;
    const int base = blockIdx.x * ROWS_PER_BLOCK + warp * ROWS_PER_WARP; // first row

    const float INV255 = 1.0f / 255.0f;

    const int plane = base / H_IMG;          // flattened (b,t,c); same for all 8 rows
    const int i0    = base % H_IMG;
    const int b     = plane / TC;

    const int sx = __ldg(&shift[2 * b + 0]);
    const int sy = __ldg(&shift[2 * b + 1]);
    const int d  = sx - PAD;                 // in [-4, 4]

    // x source columns, shared by all rows (computed once per warp)
    const int x0 = min(max(lane +  0 + d, 0), W_IMG - 1);
    const int x1 = min(max(lane + 32 + d, 0), W_IMG - 1);
    const int x2 = min(max(lane + 64 + d, 0), W_IMG - 1);

    const float* sp = img + (size_t)plane * (H_IMG * W_IMG);
    float*       dp = out + (size_t)base  * W_IMG;

    // ---- front-batch all 24 independent loads (deep MLP) ----
    float v[ROWS_PER_WARP][3];
    #pragma unroll
    for (int k = 0; k < ROWS_PER_WARP; k++) {
        const int sY = min(max(i0 + k + sy - PAD, 0), H_IMG - 1);
        const float* r = sp + sY * W_IMG;
        v[k][0] = __ldg(r + x0);
        v[k][1] = __ldg(r + x1);
        v[k][2] = __ldg(r + x2);
    }

    // ---- normalize + aligned contiguous stores ----
    #pragma unroll
    for (int k = 0; k < ROWS_PER_WARP; k++) {
        float* w = dp + k * W_IMG;
        w[lane +  0] = fmaf(v[k][0], INV255, -0.5f);
        w[lane + 32] = fmaf(v[k][1], INV255, -0.5f);
        w[lane + 64] = fmaf(v[k][2], INV255, -0.5f);
    }
}

extern "C" void kernel_launch(void* const* d_in, const int* in_sizes, int n_in,
                              void* d_out, int out_size)
{
    const float* img   = (const float*)d_in[0];
    const int*   shift = (const int*)d_in[1];
    float*       out   = (float*)d_out;

    shift_img_kernel<<<NBLOCKS, THREADS>>>(img, shift, out);
}